// round 6
// baseline (speedup 1.0000x reference)
#include <cuda_runtime.h>
#include <cuda_bf16.h>
#include <stdint.h>

#define T_  128
#define B_  1024
#define D_  96
#define H_  128
#define BH  (B_ * H_)      // 131072
#define NSL 129

#define BETA   0.9f
#define THRESH 0.5f

// Prefix sums over time of C[t] = x_t @ W_in^T
__device__ float g_P[(size_t)NSL * BH];   // ~67.6 MB

// ---------------------------------------------------------------------------
// Kernel 1: C = X @ W_in^T  (unchanged)
// ---------------------------------------------------------------------------
__global__ void k_gemm_in(const float* __restrict__ x, const float* __restrict__ Win) {
    extern __shared__ float sm[];
    float* Ws = sm;                // [96][129]
    float* As = sm + 96 * 129;     // [64][96]
    const int tid  = threadIdx.x;
    const int row0 = blockIdx.x * 64;

    for (int idx = tid; idx < H_ * D_; idx += 512) {
        int h = idx / D_, k = idx - h * D_;
        Ws[k * 129 + h] = Win[idx];
    }
    for (int idx = tid; idx < 64 * D_; idx += 512)
        As[idx] = x[(size_t)row0 * D_ + idx];
    __syncthreads();

    const int tx = tid & 31, ty = tid >> 5;
    const int r0 = ty * 4;
    float acc[4][4] = {};
    #pragma unroll 2
    for (int k = 0; k < D_; ++k) {
        float a[4];
        #pragma unroll
        for (int i = 0; i < 4; ++i) a[i] = As[(r0 + i) * 96 + k];
        #pragma unroll
        for (int j = 0; j < 4; ++j) {
            float w = Ws[k * 129 + tx + 32 * j];
            #pragma unroll
            for (int i = 0; i < 4; ++i) acc[i][j] += a[i] * w;
        }
    }
    #pragma unroll
    for (int i = 0; i < 4; ++i)
        #pragma unroll
        for (int j = 0; j < 4; ++j)
            g_P[(size_t)BH + (size_t)(row0 + r0 + i) * H_ + tx + 32 * j] = acc[i][j];
}

// ---------------------------------------------------------------------------
// Kernel 2: in-place prefix sum over t (unchanged)
// ---------------------------------------------------------------------------
__global__ void k_prefix() {
    const size_t tid = (size_t)blockIdx.x * blockDim.x + threadIdx.x;
    float run = 0.f;
    size_t idx = tid;
    g_P[idx] = 0.f;
    #pragma unroll 4
    for (int t = 1; t <= T_; ++t) {
        idx += BH;
        run += g_P[idx];
        g_P[idx] = run;
    }
}

// ---------------------------------------------------------------------------
// Kernel 3: SNN with exact 3-limb int8 IMMA hidden GEMM
// ---------------------------------------------------------------------------
#define STR8     144                     // 128 int8 + 16 pad (conflict-free ldmatrix)
#define W_BYTES  (128 * STR8)            // 18432 per limb
#define SM_SPK   0                       // spike tile s8       18432
#define SM_W     18432                   // 3 limbs             55296
#define SM_MEM1  73728                   // mem1 flat           65536
#define SM_MEM2  139264                  // mem2 flat           65536
#define SM_WOUT  204800                  // Wout                 1024
#define SM_MOUT  205824                  // memout               1024
#define SM_SRED  206848                  // reduction            4096
#define SM_TOTAL 215040

__device__ __forceinline__ uint32_t s2u(const void* p) {
    uint32_t a;
    asm("{ .reg .u64 t; cvta.to.shared.u64 t, %1; cvt.u32.u64 %0, t; }"
        : "=r"(a) : "l"(p));
    return a;
}

__device__ __forceinline__ void ldm4(uint32_t* r, uint32_t addr) {
    asm volatile("ldmatrix.sync.aligned.m8n8.x4.shared.b16 {%0,%1,%2,%3}, [%4];"
        : "=r"(r[0]), "=r"(r[1]), "=r"(r[2]), "=r"(r[3]) : "r"(addr));
}

__device__ __forceinline__ void imma16832(int* d, const uint32_t* a,
                                          uint32_t b0, uint32_t b1) {
    asm volatile(
        "mma.sync.aligned.m16n8k32.row.col.s32.s8.s8.s32 "
        "{%0,%1,%2,%3}, {%4,%5,%6,%7}, {%8,%9}, {%0,%1,%2,%3};"
        : "+r"(d[0]), "+r"(d[1]), "+r"(d[2]), "+r"(d[3])
        : "r"(a[0]), "r"(a[1]), "r"(a[2]), "r"(a[3]), "r"(b0), "r"(b1));
}

__global__ void __launch_bounds__(512, 1)
k_snn_imma(const float* __restrict__ Wh0, const float* __restrict__ Wout,
           const float* __restrict__ vx, const float* __restrict__ vy,
           float* __restrict__ out)
{
    extern __shared__ char smc[];
    const uint32_t smb = s2u(smc);
    float* sWout  = (float*)(smc + SM_WOUT);   // [2][128]
    float* memout = (float*)(smc + SM_MOUT);   // [256]

    const int tid  = threadIdx.x;
    const int w    = tid >> 5;
    const int lane = tid & 31;
    const int mg   = w & 3;        // 4 m-groups of 32 rows
    const int ng   = w >> 2;       // 4 n-groups of 32 cols
    const int t    = blockIdx.x >> 3;
    const int b0   = (blockIdx.x & 7) << 7;

    // ---- exact 3-limb int8 decomposition of round(Wh0 * 2^24) ----
    for (int idx = tid; idx < H_ * H_; idx += 512) {
        int n = idx >> 7, k = idx & 127;
        int q = __float2int_rn(Wh0[idx] * 16777216.f);   // |q| < 2^23
        int l0 = ((q + 128) & 255) - 128;  int q1 = (q - l0) >> 8;
        int l1 = ((q1 + 128) & 255) - 128; int l2 = (q1 - l1) >> 8;
        int off = n * STR8 + k;
        *(int8_t*)(smc + SM_W + 0 * W_BYTES + off) = (int8_t)l0;
        *(int8_t*)(smc + SM_W + 1 * W_BYTES + off) = (int8_t)l1;
        *(int8_t*)(smc + SM_W + 2 * W_BYTES + off) = (int8_t)l2;
    }
    if (tid < 256) { sWout[tid] = Wout[tid]; memout[tid] = 0.f; }
    {   // zero mem1 (slots 0..15) and mem2 (slots 0..15), per-thread flat float2
        const float2 z = make_float2(0.f, 0.f);
        #pragma unroll
        for (int i = 0; i < 16; ++i) {
            *(float2*)(smc + SM_MEM1 + ((size_t)i * 512 + tid) * 8) = z;
            *(float2*)(smc + SM_MEM2 + ((size_t)i * 512 + tid) * 8) = z;
        }
    }
    __syncthreads();

    const int r0base = 32 * mg + (lane >> 2);
    const int cbase  = 32 * ng + 2 * (lane & 3);
    const uint32_t aLdBase = smb + SM_SPK + (32 * mg + (lane & 15)) * STR8
                           + ((lane >> 4) << 4);
    const uint32_t bLdBase = smb + SM_W + (32 * ng + (lane & 15)) * STR8
                           + ((lane >> 4) << 4);

    for (int s = 0; s < 7; ++s) {
        // ---- window bounds ----
        int lo_, hi_;
        if (t >= 49) { lo_ = t - 49 + 7 * s; hi_ = lo_ + 7; }
        else {
            int j0 = 7 * s; if (j0 < 1) j0 = 1;
            int j1 = 7 * s + 6; if (j1 > t + 1) j1 = t + 1;
            lo_ = j0 - 1;
            hi_ = (j1 >= j0) ? j1 : lo_;
        }
        const float* __restrict__ Phi = g_P + (size_t)hi_ * BH;
        const float* __restrict__ Plo = g_P + (size_t)lo_ * BH;

        // ---- layer 1: exact fp32, spikes -> s8 {0,1} into smem tile ----
        #pragma unroll
        for (int mt = 0; mt < 2; ++mt)
            #pragma unroll
            for (int h = 0; h < 2; ++h)
                #pragma unroll
                for (int nt = 0; nt < 4; ++nt) {
                    const int idx = (mt * 2 + h) * 4 + nt;
                    const int r = r0base + 16 * mt + 8 * h;
                    const int c = cbase + 8 * nt;
                    const size_t o = (size_t)(b0 + r) * H_ + c;
                    float2 ph = *(const float2*)(Phi + o);
                    float2 pl = *(const float2*)(Plo + o);
                    float2* m1p = (float2*)(smc + SM_MEM1 + ((size_t)idx * 512 + tid) * 8);
                    float2 m1 = *m1p;
                    float nx = (m1.x > THRESH) ? 0.f : fmaf(BETA, m1.x, ph.x - pl.x);
                    float ny = (m1.y > THRESH) ? 0.f : fmaf(BETA, m1.y, ph.y - pl.y);
                    *m1p = make_float2(nx, ny);
                    uint16_t sp = (uint16_t)((nx > THRESH ? 1u : 0u)
                                           | (ny > THRESH ? 0x100u : 0u));
                    *(uint16_t*)(smc + SM_SPK + r * STR8 + c) = sp;
                }
        __syncthreads();

        // ---- hidden GEMM: Sint = sum_k spk * q  (exact int32), limb-outer ----
        int Sint[2][4][4];
        #pragma unroll
        for (int mt = 0; mt < 2; ++mt)
            #pragma unroll
            for (int nt = 0; nt < 4; ++nt)
                #pragma unroll
                for (int e = 0; e < 4; ++e) Sint[mt][nt][e] = 0;

        #pragma unroll
        for (int limb = 2; limb >= 0; --limb) {
            int acc[2][4][4];
            #pragma unroll
            for (int mt = 0; mt < 2; ++mt)
                #pragma unroll
                for (int nt = 0; nt < 4; ++nt)
                    #pragma unroll
                    for (int e = 0; e < 4; ++e) acc[mt][nt][e] = 0;

            const uint32_t bB = bLdBase + limb * W_BYTES;
            #pragma unroll
            for (int ks = 0; ks < 4; ++ks) {
                uint32_t a[2][4], b0r[4], b1r[4];
                #pragma unroll
                for (int mt = 0; mt < 2; ++mt)
                    ldm4(a[mt], aLdBase + mt * (16 * STR8) + ks * 32);
                ldm4(b0r, bB + ks * 32);                    // n-rows 0..15 of slice
                ldm4(b1r, bB + 16 * STR8 + ks * 32);        // n-rows 16..31
                #pragma unroll
                for (int mt = 0; mt < 2; ++mt) {
                    imma16832(acc[mt][0], a[mt], b0r[0], b0r[2]);
                    imma16832(acc[mt][1], a[mt], b0r[1], b0r[3]);
                    imma16832(acc[mt][2], a[mt], b1r[0], b1r[2]);
                    imma16832(acc[mt][3], a[mt], b1r[1], b1r[3]);
                }
            }
            #pragma unroll
            for (int mt = 0; mt < 2; ++mt)
                #pragma unroll
                for (int nt = 0; nt < 4; ++nt)
                    #pragma unroll
                    for (int e = 0; e < 4; ++e)
                        Sint[mt][nt][e] = (Sint[mt][nt][e] << 8) + acc[mt][nt][e];
        }

        // ---- layer 2 + output projection partials ----
        float sred_p[4][2];            // [mt*2+h][o]
        #pragma unroll
        for (int r = 0; r < 4; ++r) sred_p[r][0] = sred_p[r][1] = 0.f;

        #pragma unroll
        for (int nt = 0; nt < 4; ++nt) {
            const int c = cbase + 8 * nt;
            const float2 w0 = *(const float2*)(sWout + c);
            const float2 w1 = *(const float2*)(sWout + 128 + c);
            #pragma unroll
            for (int mt = 0; mt < 2; ++mt) {
                const int idx = (mt * 2) * 4 + nt;   // float2 slot pair base
                #pragma unroll
                for (int h = 0; h < 2; ++h) {
                    float2* m2p = (float2*)(smc + SM_MEM2
                                  + ((size_t)(idx + h * 4) * 512 + tid) * 8);
                    float2 m2 = *m2p;
                    float cx = (float)Sint[mt][nt][2 * h + 0] * 5.9604644775390625e-08f;
                    float cy = (float)Sint[mt][nt][2 * h + 1] * 5.9604644775390625e-08f;
                    float nx = (m2.x > THRESH) ? 0.f : fmaf(BETA, m2.x, cx);
                    float ny = (m2.y > THRESH) ? 0.f : fmaf(BETA, m2.y, cy);
                    *m2p = make_float2(nx, ny);
                    float sx = (nx > THRESH) ? 1.f : 0.f;
                    float sy = (ny > THRESH) ? 1.f : 0.f;
                    sred_p[mt * 2 + h][0] = fmaf(sx, w0.x, fmaf(sy, w0.y, sred_p[mt * 2 + h][0]));
                    sred_p[mt * 2 + h][1] = fmaf(sx, w1.x, fmaf(sy, w1.y, sred_p[mt * 2 + h][1]));
                }
            }
        }
        // butterfly over the 4 lanes sharing each row
        #pragma unroll
        for (int r = 0; r < 4; ++r)
            #pragma unroll
            for (int o = 0; o < 2; ++o) {
                float v = sred_p[r][o];
                v += __shfl_xor_sync(0xffffffffu, v, 1);
                v += __shfl_xor_sync(0xffffffffu, v, 2);
                sred_p[r][o] = v;
            }
        if ((lane & 3) == 0) {
            #pragma unroll
            for (int mt = 0; mt < 2; ++mt)
                #pragma unroll
                for (int h = 0; h < 2; ++h) {
                    const int row = r0base + 16 * mt + 8 * h;
                    *(float*)(smc + SM_SRED + ((row * 2 + 0) * 4 + ng) * 4) = sred_p[mt * 2 + h][0];
                    *(float*)(smc + SM_SRED + ((row * 2 + 1) * 4 + ng) * 4) = sred_p[mt * 2 + h][1];
                }
        }
        __syncthreads();
        if (tid < 256) {
            const float4 v = *(const float4*)(smc + SM_SRED + tid * 16);
            float sum = (v.x + v.y) + (v.z + v.w);
            memout[tid] = fmaf(BETA, memout[tid], sum);
        }
        // next sred writes only happen after the next spk __syncthreads
    }

    // ---- epilogue ----
    if (tid < 256) {
        const int row = tid >> 1, o = tid & 1;
        const float v = o ? vy[0] : vx[0];
        out[((size_t)t * B_ + b0 + row) * 2 + o] = memout[tid] * v;
    }
}

// ---------------------------------------------------------------------------
extern "C" void kernel_launch(void* const* d_in, const int* in_sizes, int n_in,
                              void* d_out, int out_size) {
    const float* x    = (const float*)d_in[0];
    const float* Win  = (const float*)d_in[1];
    const float* Wh0  = (const float*)d_in[2];
    const float* Wout = (const float*)d_in[3];
    const float* vx   = (const float*)d_in[4];
    const float* vy   = (const float*)d_in[5];
    float* out = (float*)d_out;

    const int smem1 = (96 * 129 + 64 * 96) * 4;   // 74112 B
    cudaFuncSetAttribute(k_gemm_in,  cudaFuncAttributeMaxDynamicSharedMemorySize, smem1);
    cudaFuncSetAttribute(k_snn_imma, cudaFuncAttributeMaxDynamicSharedMemorySize, SM_TOTAL);

    k_gemm_in<<<(T_ * B_) / 64, 512, smem1>>>(x, Win);
    k_prefix<<<BH / 256, 256>>>();
    k_snn_imma<<<T_ * 8, 512, SM_TOTAL>>>(Wh0, Wout, vx, vy, out);
}

// round 7
// speedup vs baseline: 1.8758x; 1.8758x over previous
#include <cuda_runtime.h>
#include <cuda_fp16.h>
#include <stdint.h>

#define T_  128
#define B_  1024
#define D_  96
#define H_  128
#define BH  (B_ * H_)      // 131072
#define NSL 129

#define BETA   0.9f
#define THRESH 0.5f

// Prefix sums over time of C[t] = x_t @ W_in^T
__device__ float g_P[(size_t)NSL * BH];   // ~67.6 MB

// ---------------------------------------------------------------------------
// Kernel 1: C = X @ W_in^T.  128x128 block, 512 thr, 8x4 micro-tile.
// ---------------------------------------------------------------------------
__global__ void __launch_bounds__(512, 2)
k_gemm_in(const float* __restrict__ x, const float* __restrict__ Win) {
    extern __shared__ float sm[];
    float* Ws = sm;                 // [96][132]  Ws[k*132+h] = Win[h][k]
    float* As = sm + 96 * 132;      // [128][96]
    const int tid  = threadIdx.x;
    const int row0 = blockIdx.x * 128;

    for (int idx = tid; idx < H_ * D_; idx += 512) {
        int h = idx / D_, k = idx - h * D_;
        Ws[k * 132 + h] = Win[idx];             // coalesced read
    }
    {
        const float4* src = (const float4*)(x + (size_t)row0 * D_);
        float4* dst = (float4*)As;
        for (int i = tid; i < 128 * D_ / 4; i += 512) dst[i] = src[i];
    }
    __syncthreads();

    const int tx = tid & 31, ty = tid >> 5;
    const int r0 = ty * 8;
    const int c0 = tx * 4;
    float acc[8][4] = {};
    #pragma unroll 2
    for (int k = 0; k < D_; ++k) {
        const float4 w = *(const float4*)(Ws + k * 132 + c0);   // LDS.128 conflict-free
        #pragma unroll
        for (int i = 0; i < 8; ++i) {
            const float a = As[(r0 + i) * D_ + k];              // broadcast
            acc[i][0] = fmaf(a, w.x, acc[i][0]);
            acc[i][1] = fmaf(a, w.y, acc[i][1]);
            acc[i][2] = fmaf(a, w.z, acc[i][2]);
            acc[i][3] = fmaf(a, w.w, acc[i][3]);
        }
    }
    #pragma unroll
    for (int i = 0; i < 8; ++i)
        *(float4*)(g_P + (size_t)BH + (size_t)(row0 + r0 + i) * H_ + c0) =
            make_float4(acc[i][0], acc[i][1], acc[i][2], acc[i][3]);
}

// ---------------------------------------------------------------------------
// Kernel 2: in-place prefix sum over t (unchanged)
// ---------------------------------------------------------------------------
__global__ void k_prefix() {
    const size_t tid = (size_t)blockIdx.x * blockDim.x + threadIdx.x;
    float run = 0.f;
    size_t idx = tid;
    g_P[idx] = 0.f;
    #pragma unroll 4
    for (int t = 1; t <= T_; ++t) {
        idx += BH;
        run += g_P[idx];
        g_P[idx] = run;
    }
}

// ---------------------------------------------------------------------------
// Kernel 3: SNN, hidden GEMM = 2-term fp16 split via mma.sync HMMA
// ---------------------------------------------------------------------------
#define SPK_STR  272                     // 128 fp16 + 8 pad (16B rows)
#define W_BYTES  (128 * SPK_STR)         // 34816 per term
#define SM_SPK   0                       // spike tile          34816
#define SM_W     34816                   // 2 W terms           69632
#define SM_MEM1  104448                  // mem1 flat           65536
#define SM_WOUT  169984                  // Wout                 1024
#define SM_MOUT  171008                  // memout               1024
#define SM_SRED  172032                  // reduction            8192
#define SM_TOTAL 180224

__device__ __forceinline__ uint32_t s2u(const void* p) {
    uint32_t a;
    asm("{ .reg .u64 t; cvta.to.shared.u64 t, %1; cvt.u32.u64 %0, t; }"
        : "=r"(a) : "l"(p));
    return a;
}

__device__ __forceinline__ void ldm4(uint32_t* r, uint32_t addr) {
    asm volatile("ldmatrix.sync.aligned.m8n8.x4.shared.b16 {%0,%1,%2,%3}, [%4];"
        : "=r"(r[0]), "=r"(r[1]), "=r"(r[2]), "=r"(r[3]) : "r"(addr));
}

__device__ __forceinline__ void mma16816(float* d, const uint32_t* a,
                                         uint32_t b0, uint32_t b1) {
    asm volatile(
        "mma.sync.aligned.m16n8k16.row.col.f32.f16.f16.f32 "
        "{%0,%1,%2,%3}, {%4,%5,%6,%7}, {%8,%9}, {%0,%1,%2,%3};"
        : "+f"(d[0]), "+f"(d[1]), "+f"(d[2]), "+f"(d[3])
        : "r"(a[0]), "r"(a[1]), "r"(a[2]), "r"(a[3]), "r"(b0), "r"(b1));
}

__global__ void __launch_bounds__(512, 1)
k_snn_mma(const float* __restrict__ Wh0, const float* __restrict__ Wout,
          const float* __restrict__ vx, const float* __restrict__ vy,
          float* __restrict__ out)
{
    extern __shared__ char smc[];
    const uint32_t smb = s2u(smc);
    float* sWout  = (float*)(smc + SM_WOUT);   // [2][128]
    float* memout = (float*)(smc + SM_MOUT);   // [256]

    const int tid  = threadIdx.x;
    const int w    = tid >> 5;
    const int lane = tid & 31;
    const int mg   = w & 1;        // m-group: rows 64*mg .. +63
    const int ng   = w >> 1;       // n-group: cols 16*ng .. +15
    const int t    = blockIdx.x >> 3;
    const int b0   = (blockIdx.x & 7) << 7;

    // ---- 2-term fp16 split of Wh0 (hi + residual, residual <= 2^-23 |w|) ----
    for (int idx = tid; idx < H_ * H_; idx += 512) {
        int n = idx >> 7, k = idx & 127;
        float wv = Wh0[idx];
        __half h1 = __float2half_rn(wv);
        __half h2 = __float2half_rn(wv - __half2float(h1));
        int off = n * SPK_STR + k * 2;
        *(__half*)(smc + SM_W + 0 * W_BYTES + off) = h2;   // lo first (acc order lo->hi)
        *(__half*)(smc + SM_W + 1 * W_BYTES + off) = h1;
    }
    if (tid < 256) { sWout[tid] = Wout[tid]; memout[tid] = 0.f; }
    {   // mem1 = 0 (per-thread flat layout: float2 slot i at (i*512+tid))
        const float2 z = make_float2(0.f, 0.f);
        #pragma unroll
        for (int i = 0; i < 16; ++i)
            *(float2*)(smc + SM_MEM1 + ((size_t)i * 512 + tid) * 8) = z;
    }
    __syncthreads();

    float mem2[4][2][4];
    #pragma unroll
    for (int mt = 0; mt < 4; ++mt)
        #pragma unroll
        for (int nt = 0; nt < 2; ++nt)
            #pragma unroll
            for (int e = 0; e < 4; ++e) mem2[mt][nt][e] = 0.f;

    const int r00 = 64 * mg + (lane >> 2);          // layer-1 base row
    const int cb  = 16 * ng + 2 * (lane & 3);       // layer-1 base col
    const uint32_t aLdBase = smb + SM_SPK + (64 * mg + (lane & 15)) * SPK_STR
                           + ((lane >> 4) << 4);
    const uint32_t bLdBase = smb + SM_W + (16 * ng + (lane & 15)) * SPK_STR
                           + ((lane >> 4) << 4);

    for (int s = 0; s < 7; ++s) {
        // ---- window bounds (identical to passing kernels) ----
        int lo_, hi_;
        if (t >= 49) { lo_ = t - 49 + 7 * s; hi_ = lo_ + 7; }
        else {
            int j0 = 7 * s; if (j0 < 1) j0 = 1;
            int j1 = 7 * s + 6; if (j1 > t + 1) j1 = t + 1;
            lo_ = j0 - 1;
            hi_ = (j1 >= j0) ? j1 : lo_;
        }
        const float* __restrict__ Phi = g_P + (size_t)hi_ * BH;
        const float* __restrict__ Plo = g_P + (size_t)lo_ * BH;

        // ---- layer 1: exact fp32, spikes -> fp16x2 {0,1} into smem tile ----
        #pragma unroll
        for (int mt = 0; mt < 4; ++mt)
            #pragma unroll
            for (int nt = 0; nt < 2; ++nt)
                #pragma unroll
                for (int h = 0; h < 2; ++h) {
                    const int idx = mt * 4 + nt * 2 + h;
                    const int r = r00 + 16 * mt + 8 * h;
                    const int c = cb + 8 * nt;
                    const size_t o = (size_t)(b0 + r) * H_ + c;
                    float2 ph = *(const float2*)(Phi + o);
                    float2 pl = *(const float2*)(Plo + o);
                    float2* m1p = (float2*)(smc + SM_MEM1 + ((size_t)idx * 512 + tid) * 8);
                    float2 m1 = *m1p;
                    float nx = (m1.x > THRESH) ? 0.f : fmaf(BETA, m1.x, ph.x - pl.x);
                    float ny = (m1.y > THRESH) ? 0.f : fmaf(BETA, m1.y, ph.y - pl.y);
                    *m1p = make_float2(nx, ny);
                    uint32_t wbits = (nx > THRESH ? 0x3C00u : 0u)
                                   | (ny > THRESH ? 0x3C000000u : 0u);  // fp16x2 {0,1}
                    *(uint32_t*)(smc + SM_SPK + r * SPK_STR + c * 2) = wbits;
                }
        __syncthreads();

        // ---- hidden GEMM: acc = spk @ (Wlo + Whi)^T, K=256 eff via mma.sync ----
        float acc[4][2][4];
        #pragma unroll
        for (int mt = 0; mt < 4; ++mt)
            #pragma unroll
            for (int nt = 0; nt < 2; ++nt)
                #pragma unroll
                for (int e = 0; e < 4; ++e) acc[mt][nt][e] = 0.f;

        #pragma unroll
        for (int ks = 0; ks < 8; ++ks) {
            uint32_t a[4][4];
            #pragma unroll
            for (int mt = 0; mt < 4; ++mt)
                ldm4(a[mt], aLdBase + mt * (16 * SPK_STR) + ks * 32);
            #pragma unroll
            for (int term = 0; term < 2; ++term) {
                uint32_t b[4];
                ldm4(b, bLdBase + term * W_BYTES + ks * 32);
                #pragma unroll
                for (int mt = 0; mt < 4; ++mt) {
                    mma16816(acc[mt][0], a[mt], b[0], b[2]);
                    mma16816(acc[mt][1], a[mt], b[1], b[3]);
                }
            }
        }

        // ---- layer 2 + output projection partials ----
        float sred_p[4][2][2];
        #pragma unroll
        for (int mt = 0; mt < 4; ++mt)
            #pragma unroll
            for (int h = 0; h < 2; ++h)
                sred_p[mt][h][0] = sred_p[mt][h][1] = 0.f;

        #pragma unroll
        for (int nt = 0; nt < 2; ++nt) {
            const int c = cb + 8 * nt;
            const float2 w0 = *(const float2*)(sWout + c);
            const float2 w1 = *(const float2*)(sWout + 128 + c);
            #pragma unroll
            for (int mt = 0; mt < 4; ++mt)
                #pragma unroll
                for (int e = 0; e < 4; ++e) {
                    const int h = e >> 1;
                    float m  = mem2[mt][nt][e];
                    float nm = (m > THRESH) ? 0.f : fmaf(BETA, m, acc[mt][nt][e]);
                    mem2[mt][nt][e] = nm;
                    float sp = (nm > THRESH) ? 1.f : 0.f;
                    float wa = (e & 1) ? w0.y : w0.x;
                    float wb = (e & 1) ? w1.y : w1.x;
                    sred_p[mt][h][0] = fmaf(sp, wa, sred_p[mt][h][0]);
                    sred_p[mt][h][1] = fmaf(sp, wb, sred_p[mt][h][1]);
                }
        }
        // butterfly over the 4 lanes sharing each row
        #pragma unroll
        for (int mt = 0; mt < 4; ++mt)
            #pragma unroll
            for (int h = 0; h < 2; ++h)
                #pragma unroll
                for (int o = 0; o < 2; ++o) {
                    float v = sred_p[mt][h][o];
                    v += __shfl_xor_sync(0xffffffffu, v, 1);
                    v += __shfl_xor_sync(0xffffffffu, v, 2);
                    sred_p[mt][h][o] = v;
                }
        if ((lane & 3) == 0) {
            #pragma unroll
            for (int mt = 0; mt < 4; ++mt)
                #pragma unroll
                for (int h = 0; h < 2; ++h) {
                    const int row = r00 + 16 * mt + 8 * h;
                    *(float*)(smc + SM_SRED + ((row * 2 + 0) * 8 + ng) * 4) = sred_p[mt][h][0];
                    *(float*)(smc + SM_SRED + ((row * 2 + 1) * 8 + ng) * 4) = sred_p[mt][h][1];
                }
        }
        __syncthreads();
        if (tid < 256) {
            const float4 v0 = *(const float4*)(smc + SM_SRED + tid * 32);
            const float4 v1 = *(const float4*)(smc + SM_SRED + tid * 32 + 16);
            float sum = ((v0.x + v0.y) + (v0.z + v0.w))
                      + ((v1.x + v1.y) + (v1.z + v1.w));
            memout[tid] = fmaf(BETA, memout[tid], sum);
        }
        // next sred writes happen only after the next spk __syncthreads,
        // which the tid<256 readers must also reach -> no extra sync needed
    }

    // ---- epilogue ----
    if (tid < 256) {
        const int row = tid >> 1, o = tid & 1;
        const float v = o ? vy[0] : vx[0];
        out[((size_t)t * B_ + b0 + row) * 2 + o] = memout[tid] * v;
    }
}

// ---------------------------------------------------------------------------
extern "C" void kernel_launch(void* const* d_in, const int* in_sizes, int n_in,
                              void* d_out, int out_size) {
    const float* x    = (const float*)d_in[0];
    const float* Win  = (const float*)d_in[1];
    const float* Wh0  = (const float*)d_in[2];
    const float* Wout = (const float*)d_in[3];
    const float* vx   = (const float*)d_in[4];
    const float* vy   = (const float*)d_in[5];
    float* out = (float*)d_out;

    const int smem1 = (96 * 132 + 128 * 96) * 4;   // 99840 B
    cudaFuncSetAttribute(k_gemm_in, cudaFuncAttributeMaxDynamicSharedMemorySize, smem1);
    cudaFuncSetAttribute(k_snn_mma, cudaFuncAttributeMaxDynamicSharedMemorySize, SM_TOTAL);

    k_gemm_in<<<(T_ * B_) / 128, 512, smem1>>>(x, Win);
    k_prefix<<<BH / 256, 256>>>();
    k_snn_mma<<<T_ * 8, 512, SM_TOTAL>>>(Wh0, Wout, vx, vy, out);
}

// round 8
// speedup vs baseline: 2.3487x; 1.2521x over previous
#include <cuda_runtime.h>
#include <cuda_fp16.h>
#include <stdint.h>

#define T_  128
#define B_  1024
#define D_  96
#define H_  128
#define BH  (B_ * H_)      // 131072
#define NSL 129

#define BETA   0.9f
#define THRESH 0.5f

// Prefix sums over time of C[t] = x_t @ W_in^T
__device__ float g_P[(size_t)NSL * BH];   // ~67.6 MB

// ---------------------------------------------------------------------------
// Kernel 1: C = X @ W_in^T.  128x128 block, 512 thr, 8x4 micro-tile. (unchanged)
// ---------------------------------------------------------------------------
__global__ void __launch_bounds__(512, 2)
k_gemm_in(const float* __restrict__ x, const float* __restrict__ Win) {
    extern __shared__ float sm[];
    float* Ws = sm;                 // [96][132]
    float* As = sm + 96 * 132;      // [128][96]
    const int tid  = threadIdx.x;
    const int row0 = blockIdx.x * 128;

    for (int idx = tid; idx < H_ * D_; idx += 512) {
        int h = idx / D_, k = idx - h * D_;
        Ws[k * 132 + h] = Win[idx];
    }
    {
        const float4* src = (const float4*)(x + (size_t)row0 * D_);
        float4* dst = (float4*)As;
        for (int i = tid; i < 128 * D_ / 4; i += 512) dst[i] = src[i];
    }
    __syncthreads();

    const int tx = tid & 31, ty = tid >> 5;
    const int r0 = ty * 8;
    const int c0 = tx * 4;
    float acc[8][4] = {};
    #pragma unroll 2
    for (int k = 0; k < D_; ++k) {
        const float4 w = *(const float4*)(Ws + k * 132 + c0);
        #pragma unroll
        for (int i = 0; i < 8; ++i) {
            const float a = As[(r0 + i) * D_ + k];
            acc[i][0] = fmaf(a, w.x, acc[i][0]);
            acc[i][1] = fmaf(a, w.y, acc[i][1]);
            acc[i][2] = fmaf(a, w.z, acc[i][2]);
            acc[i][3] = fmaf(a, w.w, acc[i][3]);
        }
    }
    #pragma unroll
    for (int i = 0; i < 8; ++i)
        *(float4*)(g_P + (size_t)BH + (size_t)(row0 + r0 + i) * H_ + c0) =
            make_float4(acc[i][0], acc[i][1], acc[i][2], acc[i][3]);
}

// ---------------------------------------------------------------------------
// Kernel 2: in-place prefix sum over t (unchanged)
// ---------------------------------------------------------------------------
__global__ void k_prefix() {
    const size_t tid = (size_t)blockIdx.x * blockDim.x + threadIdx.x;
    float run = 0.f;
    size_t idx = tid;
    g_P[idx] = 0.f;
    #pragma unroll 4
    for (int t = 1; t <= T_; ++t) {
        idx += BH;
        run += g_P[idx];
        g_P[idx] = run;
    }
}

// ---------------------------------------------------------------------------
// Kernel 3: SNN, 64-row tiles, 256 threads, 2 CTAs/SM for phase overlap.
// Hidden GEMM = 2-term fp16 split via mma.sync HMMA (K=256 effective).
// ---------------------------------------------------------------------------
#define SPK_STR  272                     // 128 fp16 + 8 pad (16B rows)
#define W_BYTES  (128 * SPK_STR)         // 34816 per term
#define SM_SPK   0                       // spike tile          17408
#define SM_W     17408                   // 2 W terms           69632
#define SM_WOUT  87040                   // Wout                 1024
#define SM_MOUT  88064                   // memout [64][2]        512
#define SM_SRED  88576                   // reduction [64][2][4] 2048
#define SM_TOTAL 90624

__device__ __forceinline__ uint32_t s2u(const void* p) {
    uint32_t a;
    asm("{ .reg .u64 t; cvta.to.shared.u64 t, %1; cvt.u32.u64 %0, t; }"
        : "=r"(a) : "l"(p));
    return a;
}

__device__ __forceinline__ void ldm4(uint32_t* r, uint32_t addr) {
    asm volatile("ldmatrix.sync.aligned.m8n8.x4.shared.b16 {%0,%1,%2,%3}, [%4];"
        : "=r"(r[0]), "=r"(r[1]), "=r"(r[2]), "=r"(r[3]) : "r"(addr));
}

__device__ __forceinline__ void mma16816(float* d, const uint32_t* a,
                                         uint32_t b0, uint32_t b1) {
    asm volatile(
        "mma.sync.aligned.m16n8k16.row.col.f32.f16.f16.f32 "
        "{%0,%1,%2,%3}, {%4,%5,%6,%7}, {%8,%9}, {%0,%1,%2,%3};"
        : "+f"(d[0]), "+f"(d[1]), "+f"(d[2]), "+f"(d[3])
        : "r"(a[0]), "r"(a[1]), "r"(a[2]), "r"(a[3]), "r"(b0), "r"(b1));
}

__global__ void __launch_bounds__(256, 2)
k_snn_mma(const float* __restrict__ Wh0, const float* __restrict__ Wout,
          const float* __restrict__ vx, const float* __restrict__ vy,
          float* __restrict__ out)
{
    extern __shared__ char smc[];
    const uint32_t smb = s2u(smc);
    float* sWout  = (float*)(smc + SM_WOUT);   // [2][128]
    float* memout = (float*)(smc + SM_MOUT);   // [128]

    const int tid  = threadIdx.x;
    const int w    = tid >> 5;
    const int lane = tid & 31;
    const int mg   = w & 1;        // m-group: rows 32*mg .. +31
    const int ng   = w >> 1;       // n-group: cols 32*ng .. +31
    const int t    = blockIdx.x >> 4;
    const int b0   = (blockIdx.x & 15) << 6;   // 64 rows per block

    // ---- 2-term fp16 split of Wh0 (vectorized float2 loads) ----
    {
        const float2* W2 = (const float2*)Wh0;
        for (int idx = tid; idx < H_ * H_ / 2; idx += 256) {
            int n = idx >> 6, k2 = idx & 63;          // k = 2*k2
            float2 wv = W2[idx];
            __half hx1 = __float2half_rn(wv.x);
            __half hx2 = __float2half_rn(wv.x - __half2float(hx1));
            __half hy1 = __float2half_rn(wv.y);
            __half hy2 = __float2half_rn(wv.y - __half2float(hy1));
            int off = n * SPK_STR + k2 * 4;
            *(__half2*)(smc + SM_W + 0 * W_BYTES + off) = __halves2half2(hx2, hy2);
            *(__half2*)(smc + SM_W + 1 * W_BYTES + off) = __halves2half2(hx1, hy1);
        }
    }
    sWout[tid] = Wout[tid];
    if (tid < 128) memout[tid] = 0.f;
    __syncthreads();

    // per-thread state in registers
    float mem1[2][2][4][2];   // [mt][h][nt][xy]
    float mem2[2][4][4];      // [mt][nt][e]
    #pragma unroll
    for (int mt = 0; mt < 2; ++mt)
        #pragma unroll
        for (int h = 0; h < 2; ++h)
            #pragma unroll
            for (int nt = 0; nt < 4; ++nt) {
                mem1[mt][h][nt][0] = 0.f; mem1[mt][h][nt][1] = 0.f;
            }
    #pragma unroll
    for (int mt = 0; mt < 2; ++mt)
        #pragma unroll
        for (int nt = 0; nt < 4; ++nt)
            #pragma unroll
            for (int e = 0; e < 4; ++e) mem2[mt][nt][e] = 0.f;

    const int r00 = 32 * mg + (lane >> 2);          // layer-1 base row (local)
    const int cb  = 32 * ng + 2 * (lane & 3);       // layer-1 base col
    const uint32_t aLdBase = smb + SM_SPK + (32 * mg + (lane & 15)) * SPK_STR
                           + ((lane >> 4) << 4);
    const uint32_t bLdBase = smb + SM_W + (32 * ng + (lane & 15)) * SPK_STR
                           + ((lane >> 4) << 4);

    for (int s = 0; s < 7; ++s) {
        // ---- window bounds ----
        int lo_, hi_;
        if (t >= 49) { lo_ = t - 49 + 7 * s; hi_ = lo_ + 7; }
        else {
            int j0 = 7 * s; if (j0 < 1) j0 = 1;
            int j1 = 7 * s + 6; if (j1 > t + 1) j1 = t + 1;
            lo_ = j0 - 1;
            hi_ = (j1 >= j0) ? j1 : lo_;
        }
        const float* __restrict__ Phi = g_P + (size_t)hi_ * BH;
        const float* __restrict__ Plo = g_P + (size_t)lo_ * BH;

        // ---- layer 1: exact fp32, spikes -> fp16x2 {0,1} into smem tile ----
        #pragma unroll
        for (int mt = 0; mt < 2; ++mt)
            #pragma unroll
            for (int h = 0; h < 2; ++h)
                #pragma unroll
                for (int nt = 0; nt < 4; ++nt) {
                    const int r = r00 + 16 * mt + 8 * h;
                    const int c = cb + 8 * nt;
                    const size_t o = (size_t)(b0 + r) * H_ + c;
                    float2 ph = *(const float2*)(Phi + o);
                    float2 pl = *(const float2*)(Plo + o);
                    float mx = mem1[mt][h][nt][0], my = mem1[mt][h][nt][1];
                    float nx = (mx > THRESH) ? 0.f : fmaf(BETA, mx, ph.x - pl.x);
                    float ny = (my > THRESH) ? 0.f : fmaf(BETA, my, ph.y - pl.y);
                    mem1[mt][h][nt][0] = nx; mem1[mt][h][nt][1] = ny;
                    uint32_t wbits = (nx > THRESH ? 0x3C00u : 0u)
                                   | (ny > THRESH ? 0x3C000000u : 0u);
                    *(uint32_t*)(smc + SM_SPK + r * SPK_STR + c * 2) = wbits;
                }
        __syncthreads();

        // ---- hidden GEMM: acc = spk @ (Wlo + Whi)^T ----
        float acc[2][4][4];
        #pragma unroll
        for (int mt = 0; mt < 2; ++mt)
            #pragma unroll
            for (int nt = 0; nt < 4; ++nt)
                #pragma unroll
                for (int e = 0; e < 4; ++e) acc[mt][nt][e] = 0.f;

        #pragma unroll
        for (int ks = 0; ks < 8; ++ks) {
            uint32_t a[2][4];
            #pragma unroll
            for (int mt = 0; mt < 2; ++mt)
                ldm4(a[mt], aLdBase + mt * (16 * SPK_STR) + ks * 32);
            #pragma unroll
            for (int term = 0; term < 2; ++term) {
                uint32_t b0r[4], b1r[4];
                ldm4(b0r, bLdBase + term * W_BYTES + ks * 32);
                ldm4(b1r, bLdBase + term * W_BYTES + 16 * SPK_STR + ks * 32);
                #pragma unroll
                for (int mt = 0; mt < 2; ++mt) {
                    mma16816(acc[mt][0], a[mt], b0r[0], b0r[2]);
                    mma16816(acc[mt][1], a[mt], b0r[1], b0r[3]);
                    mma16816(acc[mt][2], a[mt], b1r[0], b1r[2]);
                    mma16816(acc[mt][3], a[mt], b1r[1], b1r[3]);
                }
            }
        }

        // ---- layer 2 + output projection partials ----
        float sred_p[2][2][2];         // [mt][h][o]
        #pragma unroll
        for (int mt = 0; mt < 2; ++mt)
            #pragma unroll
            for (int h = 0; h < 2; ++h)
                sred_p[mt][h][0] = sred_p[mt][h][1] = 0.f;

        #pragma unroll
        for (int nt = 0; nt < 4; ++nt) {
            const int c = cb + 8 * nt;
            const float2 w0 = *(const float2*)(sWout + c);
            const float2 w1 = *(const float2*)(sWout + 128 + c);
            #pragma unroll
            for (int mt = 0; mt < 2; ++mt)
                #pragma unroll
                for (int e = 0; e < 4; ++e) {
                    const int h = e >> 1;
                    float m  = mem2[mt][nt][e];
                    float nm = (m > THRESH) ? 0.f : fmaf(BETA, m, acc[mt][nt][e]);
                    mem2[mt][nt][e] = nm;
                    float sp = (nm > THRESH) ? 1.f : 0.f;
                    float wa = (e & 1) ? w0.y : w0.x;
                    float wb = (e & 1) ? w1.y : w1.x;
                    sred_p[mt][h][0] = fmaf(sp, wa, sred_p[mt][h][0]);
                    sred_p[mt][h][1] = fmaf(sp, wb, sred_p[mt][h][1]);
                }
        }
        // butterfly over the 4 lanes sharing each row
        #pragma unroll
        for (int mt = 0; mt < 2; ++mt)
            #pragma unroll
            for (int h = 0; h < 2; ++h)
                #pragma unroll
                for (int o = 0; o < 2; ++o) {
                    float v = sred_p[mt][h][o];
                    v += __shfl_xor_sync(0xffffffffu, v, 1);
                    v += __shfl_xor_sync(0xffffffffu, v, 2);
                    sred_p[mt][h][o] = v;
                }
        if ((lane & 3) == 0) {
            #pragma unroll
            for (int mt = 0; mt < 2; ++mt)
                #pragma unroll
                for (int h = 0; h < 2; ++h) {
                    const int row = r00 + 16 * mt + 8 * h;
                    *(float*)(smc + SM_SRED + ((row * 2 + 0) * 4 + ng) * 4) = sred_p[mt][h][0];
                    *(float*)(smc + SM_SRED + ((row * 2 + 1) * 4 + ng) * 4) = sred_p[mt][h][1];
                }
        }
        __syncthreads();
        if (tid < 128) {
            const float4 v = *(const float4*)(smc + SM_SRED + tid * 16);
            float sum = (v.x + v.y) + (v.z + v.w);
            memout[tid] = fmaf(BETA, memout[tid], sum);
        }
        // next sred writes only happen after the next spike __syncthreads,
        // which the tid<128 readers must also reach -> no extra sync needed
    }

    // ---- epilogue ----
    if (tid < 128) {
        const int row = tid >> 1, o = tid & 1;
        const float v = o ? vy[0] : vx[0];
        out[((size_t)t * B_ + b0 + row) * 2 + o] = memout[tid] * v;
    }
}

// ---------------------------------------------------------------------------
extern "C" void kernel_launch(void* const* d_in, const int* in_sizes, int n_in,
                              void* d_out, int out_size) {
    const float* x    = (const float*)d_in[0];
    const float* Win  = (const float*)d_in[1];
    const float* Wh0  = (const float*)d_in[2];
    const float* Wout = (const float*)d_in[3];
    const float* vx   = (const float*)d_in[4];
    const float* vy   = (const float*)d_in[5];
    float* out = (float*)d_out;

    const int smem1 = (96 * 132 + 128 * 96) * 4;   // 99840 B
    cudaFuncSetAttribute(k_gemm_in, cudaFuncAttributeMaxDynamicSharedMemorySize, smem1);
    cudaFuncSetAttribute(k_snn_mma, cudaFuncAttributeMaxDynamicSharedMemorySize, SM_TOTAL);

    k_gemm_in<<<(T_ * B_) / 128, 512, smem1>>>(x, Win);
    k_prefix<<<BH / 256, 256>>>();
    k_snn_mma<<<T_ * 16, 256, SM_TOTAL>>>(Wh0, Wout, vx, vy, out);
}

// round 9
// speedup vs baseline: 2.9828x; 1.2700x over previous
#include <cuda_runtime.h>
#include <cuda_fp16.h>
#include <stdint.h>

#define T_  128
#define B_  1024
#define D_  96
#define H_  128
#define BH  (B_ * H_)      // 131072
#define NSL 129

#define BETA   0.9f
#define THRESH 0.5f

// Prefix sums over time of C[t] = x_t @ W_in^T
__device__ float g_P[(size_t)NSL * BH];           // ~67.6 MB
// layer-1 spikes as bits: [t][s][b][8 halfwords of 16 h-bits]
__device__ uint16_t g_S[(size_t)T_ * 7 * B_ * 8]; // 14.7 MB

// ---------------------------------------------------------------------------
// Kernel 1: C = X @ W_in^T  (unchanged)
// ---------------------------------------------------------------------------
__global__ void __launch_bounds__(512, 2)
k_gemm_in(const float* __restrict__ x, const float* __restrict__ Win) {
    extern __shared__ float sm[];
    float* Ws = sm;                 // [96][132]
    float* As = sm + 96 * 132;      // [128][96]
    const int tid  = threadIdx.x;
    const int row0 = blockIdx.x * 128;

    for (int idx = tid; idx < H_ * D_; idx += 512) {
        int h = idx / D_, k = idx - h * D_;
        Ws[k * 132 + h] = Win[idx];
    }
    {
        const float4* src = (const float4*)(x + (size_t)row0 * D_);
        float4* dst = (float4*)As;
        for (int i = tid; i < 128 * D_ / 4; i += 512) dst[i] = src[i];
    }
    __syncthreads();

    const int tx = tid & 31, ty = tid >> 5;
    const int r0 = ty * 8;
    const int c0 = tx * 4;
    float acc[8][4] = {};
    #pragma unroll 2
    for (int k = 0; k < D_; ++k) {
        const float4 w = *(const float4*)(Ws + k * 132 + c0);
        #pragma unroll
        for (int i = 0; i < 8; ++i) {
            const float a = As[(r0 + i) * D_ + k];
            acc[i][0] = fmaf(a, w.x, acc[i][0]);
            acc[i][1] = fmaf(a, w.y, acc[i][1]);
            acc[i][2] = fmaf(a, w.z, acc[i][2]);
            acc[i][3] = fmaf(a, w.w, acc[i][3]);
        }
    }
    #pragma unroll
    for (int i = 0; i < 8; ++i)
        *(float4*)(g_P + (size_t)BH + (size_t)(row0 + r0 + i) * H_ + c0) =
            make_float4(acc[i][0], acc[i][1], acc[i][2], acc[i][3]);
}

// ---------------------------------------------------------------------------
// Kernel 2: in-place prefix sum over t (unchanged)
// ---------------------------------------------------------------------------
__global__ void k_prefix() {
    const size_t tid = (size_t)blockIdx.x * blockDim.x + threadIdx.x;
    float run = 0.f;
    size_t idx = tid;
    g_P[idx] = 0.f;
    #pragma unroll 4
    for (int t = 1; t <= T_; ++t) {
        idx += BH;
        run += g_P[idx];
        g_P[idx] = run;
    }
}

// ---------------------------------------------------------------------------
// Kernel 3: layer-1 recurrence -> spike bits.  High occupancy, carry reuse.
// Thread handles (t, b, 16 h-values).  Arithmetic bit-identical to R8.
// ---------------------------------------------------------------------------
__global__ void __launch_bounds__(256)
k_layer1() {
    const int t     = blockIdx.x >> 5;            // 32 blocks per t
    const int chunk = blockIdx.x & 31;
    const int tid   = threadIdx.x;
    const int b     = chunk * 32 + (tid >> 3);
    const int c     = tid & 7;                    // h base = 16*c
    const size_t rowoff = (size_t)b * H_ + 16 * c;

    float m1[16], carry[16];
    #pragma unroll
    for (int i = 0; i < 16; ++i) m1[i] = 0.f;
    int carrySlice = -1;

    for (int s = 0; s < 7; ++s) {
        int lo_, hi_;
        if (t >= 49) { lo_ = t - 49 + 7 * s; hi_ = lo_ + 7; }
        else {
            int j0 = 7 * s; if (j0 < 1) j0 = 1;
            int j1 = 7 * s + 6; if (j1 > t + 1) j1 = t + 1;
            lo_ = j0 - 1;
            hi_ = (j1 >= j0) ? j1 : lo_;
        }
        const float4* Ph = (const float4*)(g_P + (size_t)hi_ * BH + rowoff);

        float cur[16];
        if (lo_ == carrySlice) {
            #pragma unroll
            for (int q = 0; q < 4; ++q) {
                float4 ph = Ph[q];
                cur[4*q+0] = ph.x - carry[4*q+0];  carry[4*q+0] = ph.x;
                cur[4*q+1] = ph.y - carry[4*q+1];  carry[4*q+1] = ph.y;
                cur[4*q+2] = ph.z - carry[4*q+2];  carry[4*q+2] = ph.z;
                cur[4*q+3] = ph.w - carry[4*q+3];  carry[4*q+3] = ph.w;
            }
        } else {
            const float4* Pl = (const float4*)(g_P + (size_t)lo_ * BH + rowoff);
            #pragma unroll
            for (int q = 0; q < 4; ++q) {
                float4 ph = Ph[q];
                float4 pl = Pl[q];
                cur[4*q+0] = ph.x - pl.x;  carry[4*q+0] = ph.x;
                cur[4*q+1] = ph.y - pl.y;  carry[4*q+1] = ph.y;
                cur[4*q+2] = ph.z - pl.z;  carry[4*q+2] = ph.z;
                cur[4*q+3] = ph.w - pl.w;  carry[4*q+3] = ph.w;
            }
        }
        carrySlice = hi_;

        uint32_t bits = 0;
        #pragma unroll
        for (int i = 0; i < 16; ++i) {
            float m  = m1[i];
            float nm = (m > THRESH) ? 0.f : fmaf(BETA, m, cur[i]);
            m1[i] = nm;
            bits |= (nm > THRESH ? 1u : 0u) << i;
        }
        g_S[(((size_t)t * 7 + s) * B_ + b) * 8 + c] = (uint16_t)bits;
    }
}

// ---------------------------------------------------------------------------
// Kernel 4: hidden GEMM + layer 2 + output.  No per-step global loads.
// 64-row tiles, 256 threads, 2 CTAs/SM.  2-term fp16 split HMMA.
// ---------------------------------------------------------------------------
#define SPK_STR  272                     // 128 fp16 + 8 pad
#define W_BYTES  (128 * SPK_STR)         // 34816 per term
#define SM_SPK   0                       // spike tile          17408
#define SM_W     17408                   // 2 W terms           69632
#define SM_WOUT  87040                   // Wout                 1024
#define SM_MOUT  88064                   // memout [64][2]        512
#define SM_SRED  88576                   // reduction [64][2][4] 2048
#define SM_TOTAL 90624

__device__ __forceinline__ uint32_t s2u(const void* p) {
    uint32_t a;
    asm("{ .reg .u64 t; cvta.to.shared.u64 t, %1; cvt.u32.u64 %0, t; }"
        : "=r"(a) : "l"(p));
    return a;
}

__device__ __forceinline__ void ldm4(uint32_t* r, uint32_t addr) {
    asm volatile("ldmatrix.sync.aligned.m8n8.x4.shared.b16 {%0,%1,%2,%3}, [%4];"
        : "=r"(r[0]), "=r"(r[1]), "=r"(r[2]), "=r"(r[3]) : "r"(addr));
}

__device__ __forceinline__ void mma16816(float* d, const uint32_t* a,
                                         uint32_t b0, uint32_t b1) {
    asm volatile(
        "mma.sync.aligned.m16n8k16.row.col.f32.f16.f16.f32 "
        "{%0,%1,%2,%3}, {%4,%5,%6,%7}, {%8,%9}, {%0,%1,%2,%3};"
        : "+f"(d[0]), "+f"(d[1]), "+f"(d[2]), "+f"(d[3])
        : "r"(a[0]), "r"(a[1]), "r"(a[2]), "r"(a[3]), "r"(b0), "r"(b1));
}

__global__ void __launch_bounds__(256, 2)
k_snn_b(const float* __restrict__ Wh0, const float* __restrict__ Wout,
        const float* __restrict__ vx, const float* __restrict__ vy,
        float* __restrict__ out)
{
    extern __shared__ char smc[];
    const uint32_t smb = s2u(smc);
    float* sWout  = (float*)(smc + SM_WOUT);   // [2][128]
    float* memout = (float*)(smc + SM_MOUT);   // [128]

    const int tid  = threadIdx.x;
    const int w    = tid >> 5;
    const int lane = tid & 31;
    const int mg   = w & 1;        // m-group: rows 32*mg .. +31
    const int ng   = w >> 1;       // n-group: cols 32*ng .. +31
    const int t    = blockIdx.x >> 4;
    const int b0   = (blockIdx.x & 15) << 6;   // 64 rows per block

    // ---- 2-term fp16 split of Wh0 ----
    {
        const float2* W2 = (const float2*)Wh0;
        for (int idx = tid; idx < H_ * H_ / 2; idx += 256) {
            int n = idx >> 6, k2 = idx & 63;
            float2 wv = W2[idx];
            __half hx1 = __float2half_rn(wv.x);
            __half hx2 = __float2half_rn(wv.x - __half2float(hx1));
            __half hy1 = __float2half_rn(wv.y);
            __half hy2 = __float2half_rn(wv.y - __half2float(hy1));
            int off = n * SPK_STR + k2 * 4;
            *(__half2*)(smc + SM_W + 0 * W_BYTES + off) = __halves2half2(hx2, hy2);
            *(__half2*)(smc + SM_W + 1 * W_BYTES + off) = __halves2half2(hx1, hy1);
        }
    }
    sWout[tid] = Wout[tid];
    if (tid < 128) memout[tid] = 0.f;

    // ---- prefetch all 7 spike words for this thread's (row, word) ----
    const int wq = tid >> 6;       // word 0..3 (32 h-bits each)
    const int re = tid & 63;       // local row for expansion
    uint32_t spw[7];
    {
        const uint32_t* Sp = (const uint32_t*)g_S;
        #pragma unroll
        for (int s = 0; s < 7; ++s)
            spw[s] = Sp[(((size_t)t * 7 + s) * B_ + b0 + re) * 4 + wq];
    }

    float mem2[2][4][4];
    #pragma unroll
    for (int mt = 0; mt < 2; ++mt)
        #pragma unroll
        for (int nt = 0; nt < 4; ++nt)
            #pragma unroll
            for (int e = 0; e < 4; ++e) mem2[mt][nt][e] = 0.f;

    const int r00 = 32 * mg + (lane >> 2);
    const int cb  = 32 * ng + 2 * (lane & 3);
    const uint32_t aLdBase = smb + SM_SPK + (32 * mg + (lane & 15)) * SPK_STR
                           + ((lane >> 4) << 4);
    const uint32_t bLdBase = smb + SM_W + (32 * ng + (lane & 15)) * SPK_STR
                           + ((lane >> 4) << 4);

    __syncthreads();

    for (int s = 0; s < 7; ++s) {
        // ---- expand spike bits -> fp16 {0,1} tile (cols 32*wq..+31 of row re) ----
        {
            const uint32_t bits = spw[s];
            uint32_t hv[16];
            #pragma unroll
            for (int j = 0; j < 16; ++j)
                hv[j] = ((bits >> (2*j)) & 1u ? 0x3C00u : 0u)
                      | ((bits >> (2*j+1)) & 1u ? 0x3C000000u : 0u);
            char* dst = smc + SM_SPK + re * SPK_STR + wq * 64;
            #pragma unroll
            for (int q = 0; q < 4; ++q)
                *(uint4*)(dst + 16 * q) = make_uint4(hv[4*q], hv[4*q+1],
                                                     hv[4*q+2], hv[4*q+3]);
        }
        __syncthreads();

        // ---- hidden GEMM: acc = spk @ (Wlo + Whi)^T ----
        float acc[2][4][4];
        #pragma unroll
        for (int mt = 0; mt < 2; ++mt)
            #pragma unroll
            for (int nt = 0; nt < 4; ++nt)
                #pragma unroll
                for (int e = 0; e < 4; ++e) acc[mt][nt][e] = 0.f;

        #pragma unroll
        for (int ks = 0; ks < 8; ++ks) {
            uint32_t a[2][4];
            #pragma unroll
            for (int mt = 0; mt < 2; ++mt)
                ldm4(a[mt], aLdBase + mt * (16 * SPK_STR) + ks * 32);
            #pragma unroll
            for (int term = 0; term < 2; ++term) {
                uint32_t b0r[4], b1r[4];
                ldm4(b0r, bLdBase + term * W_BYTES + ks * 32);
                ldm4(b1r, bLdBase + term * W_BYTES + 16 * SPK_STR + ks * 32);
                #pragma unroll
                for (int mt = 0; mt < 2; ++mt) {
                    mma16816(acc[mt][0], a[mt], b0r[0], b0r[2]);
                    mma16816(acc[mt][1], a[mt], b0r[1], b0r[3]);
                    mma16816(acc[mt][2], a[mt], b1r[0], b1r[2]);
                    mma16816(acc[mt][3], a[mt], b1r[1], b1r[3]);
                }
            }
        }

        // ---- layer 2 + output projection partials ----
        float sred_p[2][2][2];
        #pragma unroll
        for (int mt = 0; mt < 2; ++mt)
            #pragma unroll
            for (int h = 0; h < 2; ++h)
                sred_p[mt][h][0] = sred_p[mt][h][1] = 0.f;

        #pragma unroll
        for (int nt = 0; nt < 4; ++nt) {
            const int c = cb + 8 * nt;
            const float2 w0 = *(const float2*)(sWout + c);
            const float2 w1 = *(const float2*)(sWout + 128 + c);
            #pragma unroll
            for (int mt = 0; mt < 2; ++mt)
                #pragma unroll
                for (int e = 0; e < 4; ++e) {
                    const int h = e >> 1;
                    float m  = mem2[mt][nt][e];
                    float nm = (m > THRESH) ? 0.f : fmaf(BETA, m, acc[mt][nt][e]);
                    mem2[mt][nt][e] = nm;
                    float sp = (nm > THRESH) ? 1.f : 0.f;
                    float wa = (e & 1) ? w0.y : w0.x;
                    float wb = (e & 1) ? w1.y : w1.x;
                    sred_p[mt][h][0] = fmaf(sp, wa, sred_p[mt][h][0]);
                    sred_p[mt][h][1] = fmaf(sp, wb, sred_p[mt][h][1]);
                }
        }
        #pragma unroll
        for (int mt = 0; mt < 2; ++mt)
            #pragma unroll
            for (int h = 0; h < 2; ++h)
                #pragma unroll
                for (int o = 0; o < 2; ++o) {
                    float v = sred_p[mt][h][o];
                    v += __shfl_xor_sync(0xffffffffu, v, 1);
                    v += __shfl_xor_sync(0xffffffffu, v, 2);
                    sred_p[mt][h][o] = v;
                }
        if ((lane & 3) == 0) {
            #pragma unroll
            for (int mt = 0; mt < 2; ++mt)
                #pragma unroll
                for (int h = 0; h < 2; ++h) {
                    const int row = r00 + 16 * mt + 8 * h;
                    *(float*)(smc + SM_SRED + ((row * 2 + 0) * 4 + ng) * 4) = sred_p[mt][h][0];
                    *(float*)(smc + SM_SRED + ((row * 2 + 1) * 4 + ng) * 4) = sred_p[mt][h][1];
                }
        }
        __syncthreads();
        if (tid < 128) {
            const float4 v = *(const float4*)(smc + SM_SRED + tid * 16);
            float sum = (v.x + v.y) + (v.z + v.w);
            memout[tid] = fmaf(BETA, memout[tid], sum);
        }
        // next spike-tile writes happen only after the next __syncthreads
    }

    // ---- epilogue ----
    if (tid < 128) {
        const int row = tid >> 1, o = tid & 1;
        const float v = o ? vy[0] : vx[0];
        out[((size_t)t * B_ + b0 + row) * 2 + o] = memout[tid] * v;
    }
}

// ---------------------------------------------------------------------------
extern "C" void kernel_launch(void* const* d_in, const int* in_sizes, int n_in,
                              void* d_out, int out_size) {
    const float* x    = (const float*)d_in[0];
    const float* Win  = (const float*)d_in[1];
    const float* Wh0  = (const float*)d_in[2];
    const float* Wout = (const float*)d_in[3];
    const float* vx   = (const float*)d_in[4];
    const float* vy   = (const float*)d_in[5];
    float* out = (float*)d_out;

    const int smem1 = (96 * 132 + 128 * 96) * 4;   // 99840 B
    cudaFuncSetAttribute(k_gemm_in, cudaFuncAttributeMaxDynamicSharedMemorySize, smem1);
    cudaFuncSetAttribute(k_snn_b,   cudaFuncAttributeMaxDynamicSharedMemorySize, SM_TOTAL);

    k_gemm_in<<<(T_ * B_) / 128, 512, smem1>>>(x, Win);
    k_prefix<<<BH / 256, 256>>>();
    k_layer1<<<T_ * 32, 256>>>();
    k_snn_b<<<T_ * 16, 256, SM_TOTAL>>>(Wh0, Wout, vx, vy, out);
}

// round 10
// speedup vs baseline: 3.0085x; 1.0086x over previous
#include <cuda_runtime.h>
#include <cuda_fp16.h>
#include <stdint.h>

#define T_  128
#define B_  1024
#define D_  96
#define H_  128
#define BH  (B_ * H_)      // 131072
#define NSL 129

#define BETA   0.9f
#define THRESH 0.5f

// Prefix sums over time of C[t] = x_t @ W_in^T
__device__ float g_P[(size_t)NSL * BH];           // ~67.6 MB
// layer-1 spikes as bits: [t][s][b][8 halfwords of 16 h-bits]
__device__ uint16_t g_S[(size_t)T_ * 7 * B_ * 8]; // 14.7 MB

// ---------------------------------------------------------------------------
// Kernel 1: C = X @ W_in^T.  Transposed A panel: 3 LDS.128 + 32 FFMA per k.
// ---------------------------------------------------------------------------
__global__ void __launch_bounds__(512, 2)
k_gemm_in(const float* __restrict__ x, const float* __restrict__ Win) {
    extern __shared__ float sm[];
    float* Ws  = sm;                 // [96][132]  Ws[k*132+h] = Win[h][k]
    float* At  = sm + 96 * 132;      // [96][132]  At[k*132+r] = x[row0+r][k]
    const int tid  = threadIdx.x;
    const int row0 = blockIdx.x * 128;

    for (int idx = tid; idx < H_ * D_; idx += 512) {
        int h = idx / D_, k = idx - h * D_;
        Ws[k * 132 + h] = Win[idx];
    }
    for (int idx = tid; idx < 128 * D_; idx += 512) {
        int r = idx / D_, k = idx - r * D_;
        At[k * 132 + r] = x[(size_t)row0 * D_ + idx];   // coalesced read
    }
    __syncthreads();

    const int tx = tid & 31, ty = tid >> 5;
    const int r0 = ty * 8;
    const int c0 = tx * 4;
    float acc[8][4] = {};
    #pragma unroll 2
    for (int k = 0; k < D_; ++k) {
        const float4 w  = *(const float4*)(Ws + k * 132 + c0);      // spread
        const float4 aA = *(const float4*)(At + k * 132 + r0);      // broadcast
        const float4 aB = *(const float4*)(At + k * 132 + r0 + 4);  // broadcast
        const float av[8] = {aA.x, aA.y, aA.z, aA.w, aB.x, aB.y, aB.z, aB.w};
        #pragma unroll
        for (int i = 0; i < 8; ++i) {
            acc[i][0] = fmaf(av[i], w.x, acc[i][0]);
            acc[i][1] = fmaf(av[i], w.y, acc[i][1]);
            acc[i][2] = fmaf(av[i], w.z, acc[i][2]);
            acc[i][3] = fmaf(av[i], w.w, acc[i][3]);
        }
    }
    #pragma unroll
    for (int i = 0; i < 8; ++i)
        *(float4*)(g_P + (size_t)BH + (size_t)(row0 + r0 + i) * H_ + c0) =
            make_float4(acc[i][0], acc[i][1], acc[i][2], acc[i][3]);
}

// ---------------------------------------------------------------------------
// Kernel 2: in-place prefix sum over t (unchanged)
// ---------------------------------------------------------------------------
__global__ void k_prefix() {
    const size_t tid = (size_t)blockIdx.x * blockDim.x + threadIdx.x;
    float run = 0.f;
    size_t idx = tid;
    g_P[idx] = 0.f;
    #pragma unroll 4
    for (int t = 1; t <= T_; ++t) {
        idx += BH;
        run += g_P[idx];
        g_P[idx] = run;
    }
}

// ---------------------------------------------------------------------------
// Kernel 3: layer-1 recurrence -> spike bits (unchanged, bit-identical)
// ---------------------------------------------------------------------------
__global__ void __launch_bounds__(256)
k_layer1() {
    const int t     = blockIdx.x >> 5;
    const int chunk = blockIdx.x & 31;
    const int tid   = threadIdx.x;
    const int b     = chunk * 32 + (tid >> 3);
    const int c     = tid & 7;
    const size_t rowoff = (size_t)b * H_ + 16 * c;

    float m1[16], carry[16];
    #pragma unroll
    for (int i = 0; i < 16; ++i) m1[i] = 0.f;
    int carrySlice = -1;

    for (int s = 0; s < 7; ++s) {
        int lo_, hi_;
        if (t >= 49) { lo_ = t - 49 + 7 * s; hi_ = lo_ + 7; }
        else {
            int j0 = 7 * s; if (j0 < 1) j0 = 1;
            int j1 = 7 * s + 6; if (j1 > t + 1) j1 = t + 1;
            lo_ = j0 - 1;
            hi_ = (j1 >= j0) ? j1 : lo_;
        }
        const float4* Ph = (const float4*)(g_P + (size_t)hi_ * BH + rowoff);

        float cur[16];
        if (lo_ == carrySlice) {
            #pragma unroll
            for (int q = 0; q < 4; ++q) {
                float4 ph = Ph[q];
                cur[4*q+0] = ph.x - carry[4*q+0];  carry[4*q+0] = ph.x;
                cur[4*q+1] = ph.y - carry[4*q+1];  carry[4*q+1] = ph.y;
                cur[4*q+2] = ph.z - carry[4*q+2];  carry[4*q+2] = ph.z;
                cur[4*q+3] = ph.w - carry[4*q+3];  carry[4*q+3] = ph.w;
            }
        } else {
            const float4* Pl = (const float4*)(g_P + (size_t)lo_ * BH + rowoff);
            #pragma unroll
            for (int q = 0; q < 4; ++q) {
                float4 ph = Ph[q];
                float4 pl = Pl[q];
                cur[4*q+0] = ph.x - pl.x;  carry[4*q+0] = ph.x;
                cur[4*q+1] = ph.y - pl.y;  carry[4*q+1] = ph.y;
                cur[4*q+2] = ph.z - pl.z;  carry[4*q+2] = ph.z;
                cur[4*q+3] = ph.w - pl.w;  carry[4*q+3] = ph.w;
            }
        }
        carrySlice = hi_;

        uint32_t bits = 0;
        #pragma unroll
        for (int i = 0; i < 16; ++i) {
            float m  = m1[i];
            float nm = (m > THRESH) ? 0.f : fmaf(BETA, m, cur[i]);
            m1[i] = nm;
            bits |= (nm > THRESH ? 1u : 0u) << i;
        }
        g_S[(((size_t)t * 7 + s) * B_ + b) * 8 + c] = (uint16_t)bits;
    }
}

// ---------------------------------------------------------------------------
// Kernel 4: hidden GEMM + layer 2 + output.  Double-buffered spike tile,
// single barrier per step.  64-row tiles, 256 threads, 2 CTAs/SM.
// ---------------------------------------------------------------------------
#define SPK_STR   272                    // 128 fp16 + 8 pad
#define SPK_BYTES 17408                  // 64 * SPK_STR
#define W_BYTES   (128 * SPK_STR)        // 34816 per term
#define SM_SPK0   0
#define SM_SPK1   17408
#define SM_W      34816                  // 2 terms -> ends 104448
#define SM_WOUT   104448                 // 1024
#define SM_MOUT   105472                 // 512
#define SM_SRED   105984                 // 2 x 2048
#define SM_TOTAL  110080

__device__ __forceinline__ uint32_t s2u(const void* p) {
    uint32_t a;
    asm("{ .reg .u64 t; cvta.to.shared.u64 t, %1; cvt.u32.u64 %0, t; }"
        : "=r"(a) : "l"(p));
    return a;
}

__device__ __forceinline__ void ldm4(uint32_t* r, uint32_t addr) {
    asm volatile("ldmatrix.sync.aligned.m8n8.x4.shared.b16 {%0,%1,%2,%3}, [%4];"
        : "=r"(r[0]), "=r"(r[1]), "=r"(r[2]), "=r"(r[3]) : "r"(addr));
}

__device__ __forceinline__ void mma16816(float* d, const uint32_t* a,
                                         uint32_t b0, uint32_t b1) {
    asm volatile(
        "mma.sync.aligned.m16n8k16.row.col.f32.f16.f16.f32 "
        "{%0,%1,%2,%3}, {%4,%5,%6,%7}, {%8,%9}, {%0,%1,%2,%3};"
        : "+f"(d[0]), "+f"(d[1]), "+f"(d[2]), "+f"(d[3])
        : "r"(a[0]), "r"(a[1]), "r"(a[2]), "r"(a[3]), "r"(b0), "r"(b1));
}

__global__ void __launch_bounds__(256, 2)
k_snn_b(const float* __restrict__ Wh0, const float* __restrict__ Wout,
        const float* __restrict__ vx, const float* __restrict__ vy,
        float* __restrict__ out)
{
    extern __shared__ char smc[];
    const uint32_t smb = s2u(smc);
    float* sWout  = (float*)(smc + SM_WOUT);   // [2][128]
    float* memout = (float*)(smc + SM_MOUT);   // [128]

    const int tid  = threadIdx.x;
    const int w    = tid >> 5;
    const int lane = tid & 31;
    const int mg   = w & 1;
    const int ng   = w >> 1;
    const int t    = blockIdx.x >> 4;
    const int b0   = (blockIdx.x & 15) << 6;

    // ---- 2-term fp16 split of Wh0 ----
    {
        const float2* W2 = (const float2*)Wh0;
        for (int idx = tid; idx < H_ * H_ / 2; idx += 256) {
            int n = idx >> 6, k2 = idx & 63;
            float2 wv = W2[idx];
            __half hx1 = __float2half_rn(wv.x);
            __half hx2 = __float2half_rn(wv.x - __half2float(hx1));
            __half hy1 = __float2half_rn(wv.y);
            __half hy2 = __float2half_rn(wv.y - __half2float(hy1));
            int off = n * SPK_STR + k2 * 4;
            *(__half2*)(smc + SM_W + 0 * W_BYTES + off) = __halves2half2(hx2, hy2);
            *(__half2*)(smc + SM_W + 1 * W_BYTES + off) = __halves2half2(hx1, hy1);
        }
    }
    sWout[tid] = Wout[tid];
    if (tid < 128) memout[tid] = 0.f;

    // ---- prefetch all 7 spike words for this thread's (row, word) ----
    const int wq = tid >> 6;
    const int re = tid & 63;
    uint32_t spw[7];
    {
        const uint32_t* Sp = (const uint32_t*)g_S;
        #pragma unroll
        for (int s = 0; s < 7; ++s)
            spw[s] = Sp[(((size_t)t * 7 + s) * B_ + b0 + re) * 4 + wq];
    }

    float mem2[2][4][4];
    #pragma unroll
    for (int mt = 0; mt < 2; ++mt)
        #pragma unroll
        for (int nt = 0; nt < 4; ++nt)
            #pragma unroll
            for (int e = 0; e < 4; ++e) mem2[mt][nt][e] = 0.f;

    const int r00 = 32 * mg + (lane >> 2);
    const int cb  = 32 * ng + 2 * (lane & 3);
    const uint32_t aLd0 = smb + SM_SPK0 + (32 * mg + (lane & 15)) * SPK_STR
                        + ((lane >> 4) << 4);
    const uint32_t bLdBase = smb + SM_W + (32 * ng + (lane & 15)) * SPK_STR
                           + ((lane >> 4) << 4);
    const uint32_t expDst0 = smb + SM_SPK0 + re * SPK_STR + wq * 64;

    // ---- expand step 0 into buffer 0 ----
    {
        const uint32_t bits = spw[0];
        uint32_t hv[16];
        #pragma unroll
        for (int j = 0; j < 16; ++j)
            hv[j] = ((bits >> (2*j)) & 1u ? 0x3C00u : 0u)
                  | ((bits >> (2*j+1)) & 1u ? 0x3C000000u : 0u);
        #pragma unroll
        for (int q = 0; q < 4; ++q)
            *(uint4*)(smc + SM_SPK0 + re * SPK_STR + wq * 64 + 16 * q) =
                make_uint4(hv[4*q], hv[4*q+1], hv[4*q+2], hv[4*q+3]);
    }
    __syncthreads();

    for (int s = 0; s < 7; ++s) {
        const uint32_t aLdBase = aLd0 + (uint32_t)(s & 1) * SPK_BYTES;

        // ---- hidden GEMM: acc = spk @ (Wlo + Whi)^T ----
        float acc[2][4][4];
        #pragma unroll
        for (int mt = 0; mt < 2; ++mt)
            #pragma unroll
            for (int nt = 0; nt < 4; ++nt)
                #pragma unroll
                for (int e = 0; e < 4; ++e) acc[mt][nt][e] = 0.f;

        #pragma unroll
        for (int ks = 0; ks < 8; ++ks) {
            uint32_t a[2][4];
            #pragma unroll
            for (int mt = 0; mt < 2; ++mt)
                ldm4(a[mt], aLdBase + mt * (16 * SPK_STR) + ks * 32);
            #pragma unroll
            for (int term = 0; term < 2; ++term) {
                uint32_t b0r[4], b1r[4];
                ldm4(b0r, bLdBase + term * W_BYTES + ks * 32);
                ldm4(b1r, bLdBase + term * W_BYTES + 16 * SPK_STR + ks * 32);
                #pragma unroll
                for (int mt = 0; mt < 2; ++mt) {
                    mma16816(acc[mt][0], a[mt], b0r[0], b0r[2]);
                    mma16816(acc[mt][1], a[mt], b0r[1], b0r[3]);
                    mma16816(acc[mt][2], a[mt], b1r[0], b1r[2]);
                    mma16816(acc[mt][3], a[mt], b1r[1], b1r[3]);
                }
            }
        }

        // ---- expand step s+1 into the other buffer (overlaps MMA latency) ----
        if (s < 6) {
            const uint32_t bits = spw[s + 1];
            uint32_t hv[16];
            #pragma unroll
            for (int j = 0; j < 16; ++j)
                hv[j] = ((bits >> (2*j)) & 1u ? 0x3C00u : 0u)
                      | ((bits >> (2*j+1)) & 1u ? 0x3C000000u : 0u);
            const uint32_t dst = expDst0 + (uint32_t)((s + 1) & 1) * SPK_BYTES;
            char* dstp = smc + (dst - smb);
            #pragma unroll
            for (int q = 0; q < 4; ++q)
                *(uint4*)(dstp + 16 * q) = make_uint4(hv[4*q], hv[4*q+1],
                                                      hv[4*q+2], hv[4*q+3]);
        }

        // ---- layer 2 + output projection partials ----
        float sred_p[2][2][2];
        #pragma unroll
        for (int mt = 0; mt < 2; ++mt)
            #pragma unroll
            for (int h = 0; h < 2; ++h)
                sred_p[mt][h][0] = sred_p[mt][h][1] = 0.f;

        #pragma unroll
        for (int nt = 0; nt < 4; ++nt) {
            const int c = cb + 8 * nt;
            const float2 w0 = *(const float2*)(sWout + c);
            const float2 w1 = *(const float2*)(sWout + 128 + c);
            #pragma unroll
            for (int mt = 0; mt < 2; ++mt)
                #pragma unroll
                for (int e = 0; e < 4; ++e) {
                    const int h = e >> 1;
                    float m  = mem2[mt][nt][e];
                    float nm = (m > THRESH) ? 0.f : fmaf(BETA, m, acc[mt][nt][e]);
                    mem2[mt][nt][e] = nm;
                    float sp = (nm > THRESH) ? 1.f : 0.f;
                    float wa = (e & 1) ? w0.y : w0.x;
                    float wb = (e & 1) ? w1.y : w1.x;
                    sred_p[mt][h][0] = fmaf(sp, wa, sred_p[mt][h][0]);
                    sred_p[mt][h][1] = fmaf(sp, wb, sred_p[mt][h][1]);
                }
        }
        #pragma unroll
        for (int mt = 0; mt < 2; ++mt)
            #pragma unroll
            for (int h = 0; h < 2; ++h)
                #pragma unroll
                for (int o = 0; o < 2; ++o) {
                    float v = sred_p[mt][h][o];
                    v += __shfl_xor_sync(0xffffffffu, v, 1);
                    v += __shfl_xor_sync(0xffffffffu, v, 2);
                    sred_p[mt][h][o] = v;
                }
        char* sredBuf = smc + SM_SRED + (s & 1) * 2048;
        if ((lane & 3) == 0) {
            #pragma unroll
            for (int mt = 0; mt < 2; ++mt)
                #pragma unroll
                for (int h = 0; h < 2; ++h) {
                    const int row = r00 + 16 * mt + 8 * h;
                    *(float*)(sredBuf + ((row * 2 + 0) * 4 + ng) * 4) = sred_p[mt][h][0];
                    *(float*)(sredBuf + ((row * 2 + 1) * 4 + ng) * 4) = sred_p[mt][h][1];
                }
        }
        __syncthreads();   // single barrier per step

        if (tid < 128) {
            const float4 v = *(const float4*)(sredBuf + tid * 16);
            float sum = (v.x + v.y) + (v.z + v.w);
            memout[tid] = fmaf(BETA, memout[tid], sum);
        }
        // safe: next step writes the OTHER sred buffer and the OTHER spike
        // buffer; rewrites of this parity happen only after the next barrier.
    }

    // ---- epilogue (memout[tid] written by this same thread above) ----
    if (tid < 128) {
        const int row = tid >> 1, o = tid & 1;
        const float v = o ? vy[0] : vx[0];
        out[((size_t)t * B_ + b0 + row) * 2 + o] = memout[tid] * v;
    }
}

// ---------------------------------------------------------------------------
extern "C" void kernel_launch(void* const* d_in, const int* in_sizes, int n_in,
                              void* d_out, int out_size) {
    const float* x    = (const float*)d_in[0];
    const float* Win  = (const float*)d_in[1];
    const float* Wh0  = (const float*)d_in[2];
    const float* Wout = (const float*)d_in[3];
    const float* vx   = (const float*)d_in[4];
    const float* vy   = (const float*)d_in[5];
    float* out = (float*)d_out;

    const int smem1 = (96 * 132 + 96 * 132) * 4;   // 101376 B
    cudaFuncSetAttribute(k_gemm_in, cudaFuncAttributeMaxDynamicSharedMemorySize, smem1);
    cudaFuncSetAttribute(k_snn_b,   cudaFuncAttributeMaxDynamicSharedMemorySize, SM_TOTAL);

    k_gemm_in<<<(T_ * B_) / 128, 512, smem1>>>(x, Win);
    k_prefix<<<BH / 256, 256>>>();
    k_layer1<<<T_ * 32, 256>>>();
    k_snn_b<<<T_ * 16, 256, SM_TOTAL>>>(Wh0, Wout, vx, vy, out);
}

// round 11
// speedup vs baseline: 3.0396x; 1.0103x over previous
#include <cuda_runtime.h>
#include <cuda_fp16.h>
#include <stdint.h>

#define T_  128
#define B_  1024
#define D_  96
#define H_  128
#define BH  (B_ * H_)      // 131072
#define NSL 129

#define BETA   0.9f
#define THRESH 0.5f

// C[t] = x_t @ W_in^T stored at slice t+1 (slice 0 unused)
__device__ float g_P[(size_t)NSL * BH];           // ~67.6 MB
// layer-1 spikes as bits: [t][s][b][4 words of 32 h-bits]
__device__ uint16_t g_S[(size_t)T_ * 7 * B_ * 8]; // 14.7 MB

// ---------------------------------------------------------------------------
// Kernel 1: C = X @ W_in^T  (unchanged from R10)
// ---------------------------------------------------------------------------
__global__ void __launch_bounds__(512, 2)
k_gemm_in(const float* __restrict__ x, const float* __restrict__ Win) {
    extern __shared__ float sm[];
    float* Ws  = sm;                 // [96][132]
    float* At  = sm + 96 * 132;      // [96][132]
    const int tid  = threadIdx.x;
    const int row0 = blockIdx.x * 128;

    for (int idx = tid; idx < H_ * D_; idx += 512) {
        int h = idx / D_, k = idx - h * D_;
        Ws[k * 132 + h] = Win[idx];
    }
    for (int idx = tid; idx < 128 * D_; idx += 512) {
        int r = idx / D_, k = idx - r * D_;
        At[k * 132 + r] = x[(size_t)row0 * D_ + idx];
    }
    __syncthreads();

    const int tx = tid & 31, ty = tid >> 5;
    const int r0 = ty * 8;
    const int c0 = tx * 4;
    float acc[8][4] = {};
    #pragma unroll 2
    for (int k = 0; k < D_; ++k) {
        const float4 w  = *(const float4*)(Ws + k * 132 + c0);
        const float4 aA = *(const float4*)(At + k * 132 + r0);
        const float4 aB = *(const float4*)(At + k * 132 + r0 + 4);
        const float av[8] = {aA.x, aA.y, aA.z, aA.w, aB.x, aB.y, aB.z, aB.w};
        #pragma unroll
        for (int i = 0; i < 8; ++i) {
            acc[i][0] = fmaf(av[i], w.x, acc[i][0]);
            acc[i][1] = fmaf(av[i], w.y, acc[i][1]);
            acc[i][2] = fmaf(av[i], w.z, acc[i][2]);
            acc[i][3] = fmaf(av[i], w.w, acc[i][3]);
        }
    }
    #pragma unroll
    for (int i = 0; i < 8; ++i)
        *(float4*)(g_P + (size_t)BH + (size_t)(row0 + r0 + i) * H_ + c0) =
            make_float4(acc[i][0], acc[i][1], acc[i][2], acc[i][3]);
}

// ---------------------------------------------------------------------------
// Kernel 2: fused prefix + layer-1.  One thread per (b,h); private prefix
// ring in smem (51 slices).  Bit-identical arithmetic to the old
// k_prefix + k_layer1 pair.  Spike bits assembled via ballot.
// ---------------------------------------------------------------------------
__global__ void __launch_bounds__(256)
k_pl1() {
    extern __shared__ float ring[];               // [51][256]
    const int tid  = threadIdx.x;
    const int g    = blockIdx.x * 256 + tid;      // flat (b,h)
    const int b    = g >> 7;
    const int hw   = (g & 127) >> 5;              // u32 word index within row
    const int lane = tid & 31;
    uint32_t* Sp = (uint32_t*)g_S;

    float run = 0.f;
    ring[tid] = 0.f;                              // P[0] at slot 0
    float cnext = g_P[(size_t)BH + g];            // C[0]
    int pos_w    = 1;                             // (t+1) mod 51
    int pos_base = 0;                             // (t-49) mod 51 (valid t>=49)

    for (int t = 0; t < T_; ++t) {
        run += cnext;                             // P[t+1]
        if (t + 1 < T_) cnext = g_P[(size_t)(t + 2) * BH + g];
        ring[pos_w * 256 + tid] = run;

        float m1 = 0.f;
        const size_t outBase = (((size_t)t * 7) * B_ + b) * 4 + hw;

        if (t >= 49) {
            int p = pos_base;
            float plo = ring[p * 256 + tid];
            #pragma unroll
            for (int s = 0; s < 7; ++s) {
                p += 7; if (p >= 51) p -= 51;
                float phi = ring[p * 256 + tid];
                float cur = phi - plo;
                m1 = (m1 > THRESH) ? 0.f : fmaf(BETA, m1, cur);
                uint32_t bal = __ballot_sync(0xffffffffu, m1 > THRESH);
                if (lane == 0) Sp[outBase + (size_t)s * B_ * 4] = bal;
                plo = phi;
            }
            pos_base += 1; if (pos_base >= 51) pos_base -= 51;
        } else {
            #pragma unroll
            for (int s = 0; s < 7; ++s) {
                int j0 = 7 * s; if (j0 < 1) j0 = 1;
                int j1 = 7 * s + 6; if (j1 > t + 1) j1 = t + 1;
                int lo = j0 - 1;
                int hi = (j1 >= j0) ? j1 : lo;    // indices <= 50: no wrap
                float cur = ring[hi * 256 + tid] - ring[lo * 256 + tid];
                m1 = (m1 > THRESH) ? 0.f : fmaf(BETA, m1, cur);
                uint32_t bal = __ballot_sync(0xffffffffu, m1 > THRESH);
                if (lane == 0) Sp[outBase + (size_t)s * B_ * 4] = bal;
            }
        }
        pos_w += 1; if (pos_w >= 51) pos_w -= 51;
    }
}

// ---------------------------------------------------------------------------
// Kernel 3: hidden GEMM + layer 2 + output.  Phase-split GEMM (n-halves)
// so epilogue-A overlaps Phase-B tensor work.  64-row tiles, 256 thr,
// 2 CTAs/SM, double-buffered spike tile, 1 barrier/step.
// ---------------------------------------------------------------------------
#define SPK_STR   272
#define SPK_BYTES 17408
#define W_BYTES   (128 * SPK_STR)
#define SM_SPK0   0
#define SM_SPK1   17408
#define SM_W      34816
#define SM_WOUT   104448
#define SM_MOUT   105472
#define SM_SRED   105984
#define SM_TOTAL  110080

__device__ __forceinline__ uint32_t s2u(const void* p) {
    uint32_t a;
    asm("{ .reg .u64 t; cvta.to.shared.u64 t, %1; cvt.u32.u64 %0, t; }"
        : "=r"(a) : "l"(p));
    return a;
}

__device__ __forceinline__ void ldm4(uint32_t* r, uint32_t addr) {
    asm volatile("ldmatrix.sync.aligned.m8n8.x4.shared.b16 {%0,%1,%2,%3}, [%4];"
        : "=r"(r[0]), "=r"(r[1]), "=r"(r[2]), "=r"(r[3]) : "r"(addr));
}

__device__ __forceinline__ void mma16816(float* d, const uint32_t* a,
                                         uint32_t b0, uint32_t b1) {
    asm("mma.sync.aligned.m16n8k16.row.col.f32.f16.f16.f32 "
        "{%0,%1,%2,%3}, {%4,%5,%6,%7}, {%8,%9}, {%0,%1,%2,%3};"
        : "+f"(d[0]), "+f"(d[1]), "+f"(d[2]), "+f"(d[3])
        : "r"(a[0]), "r"(a[1]), "r"(a[2]), "r"(a[3]), "r"(b0), "r"(b1));
}

__global__ void __launch_bounds__(256, 2)
k_snn_b(const float* __restrict__ Wh0, const float* __restrict__ Wout,
        const float* __restrict__ vx, const float* __restrict__ vy,
        float* __restrict__ out)
{
    extern __shared__ char smc[];
    const uint32_t smb = s2u(smc);
    float* sWout  = (float*)(smc + SM_WOUT);
    float* memout = (float*)(smc + SM_MOUT);

    const int tid  = threadIdx.x;
    const int w    = tid >> 5;
    const int lane = tid & 31;
    const int mg   = w & 1;
    const int ng   = w >> 1;
    const int t    = blockIdx.x >> 4;
    const int b0   = (blockIdx.x & 15) << 6;

    // ---- 2-term fp16 split of Wh0 ----
    {
        const float2* W2 = (const float2*)Wh0;
        for (int idx = tid; idx < H_ * H_ / 2; idx += 256) {
            int n = idx >> 6, k2 = idx & 63;
            float2 wv = W2[idx];
            __half hx1 = __float2half_rn(wv.x);
            __half hx2 = __float2half_rn(wv.x - __half2float(hx1));
            __half hy1 = __float2half_rn(wv.y);
            __half hy2 = __float2half_rn(wv.y - __half2float(hy1));
            int off = n * SPK_STR + k2 * 4;
            *(__half2*)(smc + SM_W + 0 * W_BYTES + off) = __halves2half2(hx2, hy2);
            *(__half2*)(smc + SM_W + 1 * W_BYTES + off) = __halves2half2(hx1, hy1);
        }
    }
    sWout[tid] = Wout[tid];
    if (tid < 128) memout[tid] = 0.f;

    // ---- prefetch all 7 spike words ----
    const int wq = tid >> 6;
    const int re = tid & 63;
    uint32_t spw[7];
    {
        const uint32_t* Sp = (const uint32_t*)g_S;
        #pragma unroll
        for (int s = 0; s < 7; ++s)
            spw[s] = Sp[(((size_t)t * 7 + s) * B_ + b0 + re) * 4 + wq];
    }

    float mem2[2][4][4];
    #pragma unroll
    for (int mt = 0; mt < 2; ++mt)
        #pragma unroll
        for (int nt = 0; nt < 4; ++nt)
            #pragma unroll
            for (int e = 0; e < 4; ++e) mem2[mt][nt][e] = 0.f;

    const int r00 = 32 * mg + (lane >> 2);
    const int cb  = 32 * ng + 2 * (lane & 3);
    const uint32_t aLd0 = smb + SM_SPK0 + (32 * mg + (lane & 15)) * SPK_STR
                        + ((lane >> 4) << 4);
    const uint32_t bLdBase = smb + SM_W + (32 * ng + (lane & 15)) * SPK_STR
                           + ((lane >> 4) << 4);
    const uint32_t expDst0 = smb + SM_SPK0 + re * SPK_STR + wq * 64;

    // ---- expand step 0 into buffer 0 ----
    {
        const uint32_t bits = spw[0];
        uint32_t hv[16];
        #pragma unroll
        for (int j = 0; j < 16; ++j)
            hv[j] = ((bits >> (2*j)) & 1u ? 0x3C00u : 0u)
                  | ((bits >> (2*j+1)) & 1u ? 0x3C000000u : 0u);
        #pragma unroll
        for (int q = 0; q < 4; ++q)
            *(uint4*)(smc + SM_SPK0 + re * SPK_STR + wq * 64 + 16 * q) =
                make_uint4(hv[4*q], hv[4*q+1], hv[4*q+2], hv[4*q+3]);
    }
    __syncthreads();

    for (int s = 0; s < 7; ++s) {
        const uint32_t aLdBase = aLd0 + (uint32_t)(s & 1) * SPK_BYTES;

        float acc[2][4][4];
        #pragma unroll
        for (int mt = 0; mt < 2; ++mt)
            #pragma unroll
            for (int nt = 0; nt < 4; ++nt)
                #pragma unroll
                for (int e = 0; e < 4; ++e) acc[mt][nt][e] = 0.f;

        // ---- Phase A: n-rows 0..15 (nt 0,1) ----
        #pragma unroll
        for (int ks = 0; ks < 8; ++ks) {
            uint32_t a[2][4];
            #pragma unroll
            for (int mt = 0; mt < 2; ++mt)
                ldm4(a[mt], aLdBase + mt * (16 * SPK_STR) + ks * 32);
            #pragma unroll
            for (int term = 0; term < 2; ++term) {
                uint32_t br[4];
                ldm4(br, bLdBase + term * W_BYTES + ks * 32);
                #pragma unroll
                for (int mt = 0; mt < 2; ++mt) {
                    mma16816(acc[mt][0], a[mt], br[0], br[2]);
                    mma16816(acc[mt][1], a[mt], br[1], br[3]);
                }
            }
        }

        // ---- expand step s+1 into the other buffer ----
        if (s < 6) {
            const uint32_t bits = spw[s + 1];
            uint32_t hv[16];
            #pragma unroll
            for (int j = 0; j < 16; ++j)
                hv[j] = ((bits >> (2*j)) & 1u ? 0x3C00u : 0u)
                      | ((bits >> (2*j+1)) & 1u ? 0x3C000000u : 0u);
            char* dstp = smc + (expDst0 - smb) + ((s + 1) & 1) * SPK_BYTES;
            #pragma unroll
            for (int q = 0; q < 4; ++q)
                *(uint4*)(dstp + 16 * q) = make_uint4(hv[4*q], hv[4*q+1],
                                                      hv[4*q+2], hv[4*q+3]);
        }

        // ---- epilogue A (nt 0,1): depends only on Phase A accs ----
        float sred_p[2][2][2];
        #pragma unroll
        for (int mt = 0; mt < 2; ++mt)
            #pragma unroll
            for (int h = 0; h < 2; ++h)
                sred_p[mt][h][0] = sred_p[mt][h][1] = 0.f;

        #pragma unroll
        for (int nt = 0; nt < 2; ++nt) {
            const int c = cb + 8 * nt;
            const float2 w0 = *(const float2*)(sWout + c);
            const float2 w1 = *(const float2*)(sWout + 128 + c);
            #pragma unroll
            for (int mt = 0; mt < 2; ++mt)
                #pragma unroll
                for (int e = 0; e < 4; ++e) {
                    const int h = e >> 1;
                    float m  = mem2[mt][nt][e];
                    float nm = (m > THRESH) ? 0.f : fmaf(BETA, m, acc[mt][nt][e]);
                    mem2[mt][nt][e] = nm;
                    float sp = (nm > THRESH) ? 1.f : 0.f;
                    float wa = (e & 1) ? w0.y : w0.x;
                    float wb = (e & 1) ? w1.y : w1.x;
                    sred_p[mt][h][0] = fmaf(sp, wa, sred_p[mt][h][0]);
                    sred_p[mt][h][1] = fmaf(sp, wb, sred_p[mt][h][1]);
                }
        }

        // ---- Phase B: n-rows 16..31 (nt 2,3); overlaps epilogue A ----
        #pragma unroll
        for (int ks = 0; ks < 8; ++ks) {
            uint32_t a[2][4];
            #pragma unroll
            for (int mt = 0; mt < 2; ++mt)
                ldm4(a[mt], aLdBase + mt * (16 * SPK_STR) + ks * 32);
            #pragma unroll
            for (int term = 0; term < 2; ++term) {
                uint32_t br[4];
                ldm4(br, bLdBase + term * W_BYTES + 16 * SPK_STR + ks * 32);
                #pragma unroll
                for (int mt = 0; mt < 2; ++mt) {
                    mma16816(acc[mt][2], a[mt], br[0], br[2]);
                    mma16816(acc[mt][3], a[mt], br[1], br[3]);
                }
            }
        }

        // ---- epilogue B (nt 2,3) ----
        #pragma unroll
        for (int nt = 2; nt < 4; ++nt) {
            const int c = cb + 8 * nt;
            const float2 w0 = *(const float2*)(sWout + c);
            const float2 w1 = *(const float2*)(sWout + 128 + c);
            #pragma unroll
            for (int mt = 0; mt < 2; ++mt)
                #pragma unroll
                for (int e = 0; e < 4; ++e) {
                    const int h = e >> 1;
                    float m  = mem2[mt][nt][e];
                    float nm = (m > THRESH) ? 0.f : fmaf(BETA, m, acc[mt][nt][e]);
                    mem2[mt][nt][e] = nm;
                    float sp = (nm > THRESH) ? 1.f : 0.f;
                    float wa = (e & 1) ? w0.y : w0.x;
                    float wb = (e & 1) ? w1.y : w1.x;
                    sred_p[mt][h][0] = fmaf(sp, wa, sred_p[mt][h][0]);
                    sred_p[mt][h][1] = fmaf(sp, wb, sred_p[mt][h][1]);
                }
        }

        #pragma unroll
        for (int mt = 0; mt < 2; ++mt)
            #pragma unroll
            for (int h = 0; h < 2; ++h)
                #pragma unroll
                for (int o = 0; o < 2; ++o) {
                    float v = sred_p[mt][h][o];
                    v += __shfl_xor_sync(0xffffffffu, v, 1);
                    v += __shfl_xor_sync(0xffffffffu, v, 2);
                    sred_p[mt][h][o] = v;
                }
        char* sredBuf = smc + SM_SRED + (s & 1) * 2048;
        if ((lane & 3) == 0) {
            #pragma unroll
            for (int mt = 0; mt < 2; ++mt)
                #pragma unroll
                for (int h = 0; h < 2; ++h) {
                    const int row = r00 + 16 * mt + 8 * h;
                    *(float*)(sredBuf + ((row * 2 + 0) * 4 + ng) * 4) = sred_p[mt][h][0];
                    *(float*)(sredBuf + ((row * 2 + 1) * 4 + ng) * 4) = sred_p[mt][h][1];
                }
        }
        __syncthreads();

        if (tid < 128) {
            const float4 v = *(const float4*)(sredBuf + tid * 16);
            float sum = (v.x + v.y) + (v.z + v.w);
            memout[tid] = fmaf(BETA, memout[tid], sum);
        }
    }

    // ---- epilogue ----
    if (tid < 128) {
        const int row = tid >> 1, o = tid & 1;
        const float v = o ? vy[0] : vx[0];
        out[((size_t)t * B_ + b0 + row) * 2 + o] = memout[tid] * v;
    }
}

// ---------------------------------------------------------------------------
extern "C" void kernel_launch(void* const* d_in, const int* in_sizes, int n_in,
                              void* d_out, int out_size) {
    const float* x    = (const float*)d_in[0];
    const float* Win  = (const float*)d_in[1];
    const float* Wh0  = (const float*)d_in[2];
    const float* Wout = (const float*)d_in[3];
    const float* vx   = (const float*)d_in[4];
    const float* vy   = (const float*)d_in[5];
    float* out = (float*)d_out;

    const int smem1 = (96 * 132 + 96 * 132) * 4;   // 101376 B
    const int smem2 = 51 * 256 * 4;                // 52224 B
    cudaFuncSetAttribute(k_gemm_in, cudaFuncAttributeMaxDynamicSharedMemorySize, smem1);
    cudaFuncSetAttribute(k_pl1,     cudaFuncAttributeMaxDynamicSharedMemorySize, smem2);
    cudaFuncSetAttribute(k_snn_b,   cudaFuncAttributeMaxDynamicSharedMemorySize, SM_TOTAL);

    k_gemm_in<<<(T_ * B_) / 128, 512, smem1>>>(x, Win);
    k_pl1<<<BH / 256, 256, smem2>>>();
    k_snn_b<<<T_ * 16, 256, SM_TOTAL>>>(Wh0, Wout, vx, vy, out);
}